// round 4
// baseline (speedup 1.0000x reference)
#include <cuda_runtime.h>
#include <math.h>

#define STEPF   0.1f
#define MAXL    1024
#define MAXNS   64
#define DELAY_N 30
#define TPB     32
#define PPT     4            // pixels per thread

__device__ float2 g_aif2[MAXL];   // AIF duplicated into both lanes
__device__ int    g_idx[MAXNS];
__device__ int    g_L;

typedef unsigned long long u64;

__device__ __forceinline__ u64 fma2(u64 a, u64 b, u64 c) {
    u64 d;
    asm("fma.rn.f32x2 %0, %1, %2, %3;" : "=l"(d) : "l"(a), "l"(b), "l"(c));
    return d;
}
__device__ __forceinline__ u64 pack2(float lo, float hi) {
    u64 d; asm("mov.b64 %0, {%1, %2};" : "=l"(d) : "f"(lo), "f"(hi)); return d;
}
__device__ __forceinline__ void unpack2(u64 v, float& lo, float& hi) {
    asm("mov.b64 {%0, %1}, %2;" : "=f"(lo), "=f"(hi) : "l"(v));
}

// ---------------------------------------------------------------------------
// Prep (1 block): fine-grid AIF (interp + 3s delay) and searchsorted indices
// ---------------------------------------------------------------------------
__global__ void dce_prep_kernel(const float* __restrict__ sample_time,
                                const float* __restrict__ Cp, int ns)
{
    double t_end = (double)sample_time[ns - 1];
    int L = (int)llrint(t_end / 0.1) + 1;
    if (L > MAXL) L = MAXL;
    if (threadIdx.x == 0) g_L = L;

    for (int i = threadIdx.x; i < L; i += blockDim.x) {
        float val = 0.f;
        if (i >= DELAY_N) {
            const float t = (float)(i - DELAY_N) * STEPF;
            if (t <= sample_time[0]) {
                val = Cp[0];
            } else if (t >= sample_time[ns - 1]) {
                val = Cp[ns - 1];
            } else {
                int lo = 0, hi = ns - 1;
                while (lo + 1 < hi) {
                    int mid = (lo + hi) >> 1;
                    if (sample_time[mid] <= t) lo = mid; else hi = mid;
                }
                const float x0 = sample_time[lo], x1 = sample_time[lo + 1];
                val = Cp[lo] + (t - x0) * (Cp[lo + 1] - Cp[lo]) / (x1 - x0);
            }
        }
        g_aif2[i] = make_float2(val, val);
    }

    int jmax = ns < MAXNS ? ns : MAXNS;
    for (int j = threadIdx.x; j < jmax; j += blockDim.x) {
        const float st = sample_time[j];
        int lo = 0, hi = L;
        while (lo < hi) {
            int mid = (lo + hi) >> 1;
            if ((float)mid * STEPF < st) lo = mid + 1; else hi = mid; // same IEEE ops as jnp
        }
        g_idx[j] = lo < (L - 1) ? lo : (L - 1);
    }
}

// ---------------------------------------------------------------------------
// Main: 4 pixels/thread, packed (Sm,Sp) bi-exponential recurrence + SPGR
// ---------------------------------------------------------------------------
__global__ void __launch_bounds__(TPB)
dce_main_kernel(const float* __restrict__ param,
                float* __restrict__ out, int npix, int ns)
{
    __shared__ float2 s_aif2[MAXL];
    __shared__ int    s_idx[MAXNS];

    const int tid = threadIdx.x;
    const int L = g_L;
    for (int i = tid; i < L; i += TPB) s_aif2[i] = g_aif2[i];
    for (int j = tid; j < ns && j < MAXNS; j += TPB) s_idx[j] = g_idx[j];
    __syncthreads();

    const int base = blockIdx.x * (TPB * PPT) + tid;

    float ve[PPT], vp[PPT], cm[PPT], cpv_c[PPT], inv_she[PPT], inv_shp[PPT];
    u64 S[PPT], R[PPT];
    bool valid[PPT];

    #pragma unroll
    for (int k = 0; k < PPT; ++k) {
        int pix = base + k * TPB;
        valid[k] = pix < npix;
        int p = valid[k] ? pix : 0;

        const float vek = param[p];
        const float vpk = param[npix + p];
        const float fpp = param[2 * npix + p];
        const float ps  = param[3 * npix + p];
        ve[k] = vek; vp[k] = vpk;

        const float Te = vek / ps;
        const float T  = (vpk + vek) / fpp;
        const float Tc = vpk / fpp;
        const float s  = T + Te;
        const float disc = sqrtf(fmaxf(s * s - 4.f * Tc * Te, 0.f));
        const float inv2 = 1.f / (2.f * Tc * Te);
        const float thp = (s + disc) * inv2;
        const float thm = (s - disc) * inv2;

        const float rm = expf(-thm * STEPF);   // compounds over L steps: precise
        const float rp = expf(-thp * STEPF);
        R[k] = pack2(rm, rp);
        S[k] = 0ull;

        const float Lf  = (float)L;
        const float SEm = (-expm1f(-thm * STEPF * Lf)) / (-expm1f(-thm * STEPF));
        const float SEp = (-expm1f(-thp * STEPF * Lf)) / (-expm1f(-thp * STEPF));

        cm[k]    = 1.f - Te * thm;
        cpv_c[k] = Te * thp - 1.f;
        inv_she[k] = 1.f / (SEm - SEp);
        inv_shp[k] = 1.f / fmaf(cm[k], SEm, cpv_c[k] * SEp);
    }

    // SPGR constants
    const float cosfa = 0.98480775301220806f;   // cos(10 deg)
    const float E1    = expf(-0.00487f);
    const float M0t   = 100.f * (1.f - cosfa * E1) / (1.f - E1);
    const float bse   = 100.f - M0t * (1.f - E1) / (1.f - E1 * cosfa);

    const u64* __restrict__ aifu = reinterpret_cast<const u64*>(s_aif2);

    float* __restrict__ orow = out + base;   // advances by npix each sample

    int m = 0;
    for (int j = 0; j < ns; ++j) {
        const int target = s_idx[j];
        const int n = target - m + 1;
        #pragma unroll 4
        for (int kk = 0; kk < n; ++kk) {
            const u64 a = aifu[m + kk];
            S[0] = fma2(S[0], R[0], a);
            S[1] = fma2(S[1], R[1], a);
            S[2] = fma2(S[2], R[2], a);
            S[3] = fma2(S[3], R[3], a);
        }
        m = target + 1;

        #pragma unroll
        for (int k = 0; k < PPT; ++k) {
            float Sm, Sp;
            unpack2(S[k], Sm, Sp);
            const float ce   = inv_she[k] * (Sm - Sp);
            const float cpv  = inv_shp[k] * fmaf(cm[k], Sm, cpv_c[k] * Sp);
            const float conc = vp[k] * cpv + ve[k] * ce;
            const float E1CA = __expf(-0.00487f * fmaf(4.3f, conc, 1.0f));
            const float sig  = __fdividef(M0t * (1.f - E1CA), 1.f - E1CA * cosfa) + bse;
            if (valid[k]) orow[k * TPB] = sig;
        }
        orow += npix;
    }
}

extern "C" void kernel_launch(void* const* d_in, const int* in_sizes, int n_in,
                              void* d_out, int out_size)
{
    const float* param       = (const float*)d_in[0];
    const float* sample_time = (const float*)d_in[1];
    const float* Cp          = (const float*)d_in[2];
    float* out = (float*)d_out;

    const int ns   = in_sizes[1];
    const int npix = in_sizes[0] / 4;

    dce_prep_kernel<<<1, 64>>>(sample_time, Cp, ns);

    const int pix_per_block = TPB * PPT;
    const int blocks = (npix + pix_per_block - 1) / pix_per_block;
    dce_main_kernel<<<blocks, TPB>>>(param, out, npix, ns);
}

// round 5
// speedup vs baseline: 1.2039x; 1.2039x over previous
#include <cuda_runtime.h>
#include <math.h>

#define STEPF   0.1f
#define MAXL    1024
#define MAXNS   64
#define DELAY_N 30
#define TPB     64
#define PPT     2            // pixels per thread

__device__ float2 g_aif2[MAXL];   // AIF duplicated into both lanes
__device__ int    g_idx[MAXNS];
__device__ int    g_L;

typedef unsigned long long u64;

__device__ __forceinline__ u64 fma2(u64 a, u64 b, u64 c) {
    u64 d;
    asm("fma.rn.f32x2 %0, %1, %2, %3;" : "=l"(d) : "l"(a), "l"(b), "l"(c));
    return d;
}
__device__ __forceinline__ u64 pack2(float lo, float hi) {
    u64 d; asm("mov.b64 %0, {%1, %2};" : "=l"(d) : "f"(lo), "f"(hi)); return d;
}
__device__ __forceinline__ void unpack2(u64 v, float& lo, float& hi) {
    asm("mov.b64 {%0, %1}, %2;" : "=f"(lo), "=f"(hi) : "l"(v));
}

// ---------------------------------------------------------------------------
// Prep (1 block): stage 50-pt inputs in shared, then build fine-grid AIF
// (interp + 3s delay) and searchsorted sample indices. All searches hit smem.
// ---------------------------------------------------------------------------
__global__ void dce_prep_kernel(const float* __restrict__ sample_time,
                                const float* __restrict__ Cp, int ns)
{
    __shared__ float s_st[MAXNS];
    __shared__ float s_cp[MAXNS];

    for (int j = threadIdx.x; j < ns && j < MAXNS; j += blockDim.x) {
        s_st[j] = sample_time[j];
        s_cp[j] = Cp[j];
    }
    __syncthreads();

    double t_end = (double)s_st[ns - 1];
    int L = (int)llrint(t_end / 0.1) + 1;
    if (L > MAXL) L = MAXL;
    if (threadIdx.x == 0) g_L = L;

    for (int i = threadIdx.x; i < L; i += blockDim.x) {
        float val = 0.f;
        if (i >= DELAY_N) {
            const float t = (float)(i - DELAY_N) * STEPF;
            if (t <= s_st[0]) {
                val = s_cp[0];
            } else if (t >= s_st[ns - 1]) {
                val = s_cp[ns - 1];
            } else {
                int lo = 0, hi = ns - 1;
                while (lo + 1 < hi) {
                    int mid = (lo + hi) >> 1;
                    if (s_st[mid] <= t) lo = mid; else hi = mid;
                }
                const float x0 = s_st[lo], x1 = s_st[lo + 1];
                val = s_cp[lo] + (t - x0) * (s_cp[lo + 1] - s_cp[lo]) / (x1 - x0);
            }
        }
        g_aif2[i] = make_float2(val, val);
    }

    for (int j = threadIdx.x; j < ns && j < MAXNS; j += blockDim.x) {
        const float st = s_st[j];
        int lo = 0, hi = L;
        while (lo < hi) {
            int mid = (lo + hi) >> 1;
            if ((float)mid * STEPF < st) lo = mid + 1; else hi = mid; // same IEEE ops as jnp
        }
        g_idx[j] = lo < (L - 1) ? lo : (L - 1);
    }
}

// ---------------------------------------------------------------------------
// Main: 2 pixels/thread, packed (Sm,Sp) bi-exponential recurrence + SPGR
// ---------------------------------------------------------------------------
__global__ void __launch_bounds__(TPB)
dce_main_kernel(const float* __restrict__ param,
                float* __restrict__ out, int npix, int ns)
{
    __shared__ float2 s_aif2[MAXL];
    __shared__ int    s_idx[MAXNS];

    const int tid = threadIdx.x;
    const int L = g_L;
    for (int i = tid; i < L; i += TPB) s_aif2[i] = g_aif2[i];
    for (int j = tid; j < ns && j < MAXNS; j += TPB) s_idx[j] = g_idx[j];
    __syncthreads();

    const int base = blockIdx.x * (TPB * PPT) + tid;

    float ve[PPT], vp[PPT], cm[PPT], cpc[PPT], inv_she[PPT], inv_shp[PPT];
    u64 S[PPT], R[PPT];
    bool valid[PPT];

    #pragma unroll
    for (int k = 0; k < PPT; ++k) {
        int pix = base + k * TPB;
        valid[k] = pix < npix;
        int p = valid[k] ? pix : 0;

        const float vek = param[p];
        const float vpk = param[npix + p];
        const float fpp = param[2 * npix + p];
        const float ps  = param[3 * npix + p];
        ve[k] = vek; vp[k] = vpk;

        const float Te = vek / ps;
        const float T  = (vpk + vek) / fpp;
        const float Tc = vpk / fpp;
        const float s  = T + Te;
        const float disc = sqrtf(fmaxf(s * s - 4.f * Tc * Te, 0.f));
        const float inv2 = 1.f / (2.f * Tc * Te);
        const float thp = (s + disc) * inv2;
        const float thm = (s - disc) * inv2;

        const float rm = expf(-thm * STEPF);   // compounds over L steps: precise
        const float rp = expf(-thp * STEPF);
        R[k] = pack2(rm, rp);
        S[k] = 0ull;

        const float Lf  = (float)L;
        const float SEm = (-expm1f(-thm * STEPF * Lf)) / (-expm1f(-thm * STEPF));
        const float SEp = (-expm1f(-thp * STEPF * Lf)) / (-expm1f(-thp * STEPF));

        cm[k]  = 1.f - Te * thm;
        cpc[k] = Te * thp - 1.f;
        inv_she[k] = 1.f / (SEm - SEp);
        inv_shp[k] = 1.f / fmaf(cm[k], SEm, cpc[k] * SEp);
    }

    // SPGR constants
    const float cosfa = 0.98480775301220806f;   // cos(10 deg)
    const float E1    = expf(-0.00487f);
    const float M0t   = 100.f * (1.f - cosfa * E1) / (1.f - E1);
    const float bse   = 100.f - M0t * (1.f - E1) / (1.f - E1 * cosfa);

    const u64* __restrict__ aifu = reinterpret_cast<const u64*>(s_aif2);

    float* __restrict__ orow = out + base;   // advances by npix each sample

    int m = 0;
    for (int j = 0; j < ns; ++j) {
        const int target = s_idx[j];
        const int n = target - m + 1;
        #pragma unroll 4
        for (int kk = 0; kk < n; ++kk) {
            const u64 a = aifu[m + kk];
            S[0] = fma2(S[0], R[0], a);
            S[1] = fma2(S[1], R[1], a);
        }
        m = target + 1;

        #pragma unroll
        for (int k = 0; k < PPT; ++k) {
            float Sm, Sp;
            unpack2(S[k], Sm, Sp);
            const float ce   = inv_she[k] * (Sm - Sp);
            const float cpv  = inv_shp[k] * fmaf(cm[k], Sm, cpc[k] * Sp);
            const float conc = vp[k] * cpv + ve[k] * ce;
            const float E1CA = __expf(-0.00487f * fmaf(4.3f, conc, 1.0f));
            const float sig  = __fdividef(M0t * (1.f - E1CA), 1.f - E1CA * cosfa) + bse;
            if (valid[k]) orow[k * TPB] = sig;
        }
        orow += npix;
    }
}

extern "C" void kernel_launch(void* const* d_in, const int* in_sizes, int n_in,
                              void* d_out, int out_size)
{
    const float* param       = (const float*)d_in[0];
    const float* sample_time = (const float*)d_in[1];
    const float* Cp          = (const float*)d_in[2];
    float* out = (float*)d_out;

    const int ns   = in_sizes[1];
    const int npix = in_sizes[0] / 4;

    dce_prep_kernel<<<1, 128>>>(sample_time, Cp, ns);

    const int pix_per_block = TPB * PPT;
    const int blocks = (npix + pix_per_block - 1) / pix_per_block;
    dce_main_kernel<<<blocks, TPB>>>(param, out, npix, ns);
}